// round 4
// baseline (speedup 1.0000x reference)
#include <cuda_runtime.h>

#define NG   64      // graphs
#define NPG  256     // nodes per graph
#define EPG  1024    // edges per graph
#define NN   (NG*NPG)
#define DF   512
#define HF   1024
#define HP   256
#define NC   10

__device__ float g_f[NN];
__device__ float g_pool[2][NG][HP];

// ---------------------------------------------------------------------------
// Kernel 1: fused filtration
//   f[n] = sigmoid( sum_c relu( x[n] . W1[:,c] + b1[c] ) * w2[c] + b2 )
// Never materializes h [16384,1024]. Register-tiled: 64 nodes x 128 ch tiles.
// ---------------------------------------------------------------------------
#define MT 64
#define CT 128
#define KT 32

__global__ __launch_bounds__(256) void filt_kernel(
    const float* __restrict__ x,  const float* __restrict__ w1,
    const float* __restrict__ b1, const float* __restrict__ w2,
    const float* __restrict__ b2)
{
    __shared__ float xs[KT][MT + 1];    // k-major x tile (padded: conflict-free)
    __shared__ float ws[KT][CT + 4];    // k-major w1 tile
    __shared__ float red[MT][17];       // cross-thread channel reduction
    __shared__ float facc[MT];

    const int tid = threadIdx.x;
    const int tx  = tid & 15;           // channel group
    const int ty  = tid >> 4;           // node group
    const int n0  = blockIdx.x * MT;

    if (tid < MT) facc[tid] = 0.f;
    __syncthreads();

    for (int ct = 0; ct < HF; ct += CT) {
        float acc[4][8];
        #pragma unroll
        for (int i = 0; i < 4; i++)
            #pragma unroll
            for (int j = 0; j < 8; j++) acc[i][j] = 0.f;

        for (int k0 = 0; k0 < DF; k0 += KT) {
            // x tile: 64 nodes x 32 k, stored transposed (512 float4, 2/thread)
            #pragma unroll
            for (int r = 0; r < 2; r++) {
                int idx = tid + r * 256;
                int n   = idx >> 3;
                int kq  = idx & 7;
                float4 v = *(const float4*)&x[(size_t)(n0 + n) * DF + k0 + kq * 4];
                xs[kq*4+0][n] = v.x; xs[kq*4+1][n] = v.y;
                xs[kq*4+2][n] = v.z; xs[kq*4+3][n] = v.w;
            }
            // w1 tile: 32 k x 128 c (1024 float4, 4/thread)
            #pragma unroll
            for (int r = 0; r < 4; r++) {
                int idx = tid + r * 256;
                int kk  = idx >> 5;
                int cq  = idx & 31;
                float4 v = *(const float4*)&w1[(size_t)(k0 + kk) * HF + ct + cq * 4];
                *(float4*)&ws[kk][cq * 4] = v;
            }
            __syncthreads();

            #pragma unroll
            for (int kk = 0; kk < KT; kk++) {
                float a0 = xs[kk][ty*4+0], a1 = xs[kk][ty*4+1];
                float a2 = xs[kk][ty*4+2], a3 = xs[kk][ty*4+3];
                float4 bA = *(float4*)&ws[kk][tx*4];
                float4 bB = *(float4*)&ws[kk][64 + tx*4];
                acc[0][0] += a0*bA.x; acc[0][1] += a0*bA.y; acc[0][2] += a0*bA.z; acc[0][3] += a0*bA.w;
                acc[1][0] += a1*bA.x; acc[1][1] += a1*bA.y; acc[1][2] += a1*bA.z; acc[1][3] += a1*bA.w;
                acc[2][0] += a2*bA.x; acc[2][1] += a2*bA.y; acc[2][2] += a2*bA.z; acc[2][3] += a2*bA.w;
                acc[3][0] += a3*bA.x; acc[3][1] += a3*bA.y; acc[3][2] += a3*bA.z; acc[3][3] += a3*bA.w;
                acc[0][4] += a0*bB.x; acc[0][5] += a0*bB.y; acc[0][6] += a0*bB.z; acc[0][7] += a0*bB.w;
                acc[1][4] += a1*bB.x; acc[1][5] += a1*bB.y; acc[1][6] += a1*bB.z; acc[1][7] += a1*bB.w;
                acc[2][4] += a2*bB.x; acc[2][5] += a2*bB.y; acc[2][6] += a2*bB.z; acc[2][7] += a2*bB.w;
                acc[3][4] += a3*bB.x; acc[3][5] += a3*bB.y; acc[3][6] += a3*bB.z; acc[3][7] += a3*bB.w;
            }
            __syncthreads();
        }

        // epilogue: relu + weighted channel reduction for this channel tile
        float s0 = 0.f, s1 = 0.f, s2 = 0.f, s3 = 0.f;
        #pragma unroll
        for (int j = 0; j < 8; j++) {
            int c = ct + (j < 4 ? tx*4 + j : 64 + tx*4 + (j - 4));
            float bb = b1[c], wv = w2[c];
            s0 += fmaxf(acc[0][j] + bb, 0.f) * wv;
            s1 += fmaxf(acc[1][j] + bb, 0.f) * wv;
            s2 += fmaxf(acc[2][j] + bb, 0.f) * wv;
            s3 += fmaxf(acc[3][j] + bb, 0.f) * wv;
        }
        red[ty*4+0][tx] = s0;
        red[ty*4+1][tx] = s1;
        red[ty*4+2][tx] = s2;
        red[ty*4+3][tx] = s3;
        __syncthreads();
        if (tid < MT) {               // deterministic fixed-order reduction
            float t = 0.f;
            #pragma unroll
            for (int p = 0; p < 16; p++) t += red[tid][p];
            facc[tid] += t;
        }
        __syncthreads();
    }

    if (tid < MT) {
        float t = facc[tid] + b2[0];
        g_f[n0 + tid] = 1.f / (1.f + expf(-t));
    }
}

// ---------------------------------------------------------------------------
// Kernel 2: per-(graph, sign) 0-dim persistence + fused phi-MLP pooling.
// One CTA per (graph, filtration sign). All state in smem.
// ---------------------------------------------------------------------------
__device__ __forceinline__ unsigned int f2ord(float f) {
    unsigned int b = __float_as_uint(f);
    return b ^ (((int)b >> 31) | 0x80000000u);
}
__device__ __forceinline__ float ord2f(unsigned int o) {
    unsigned int b = (o & 0x80000000u) ? (o ^ 0x80000000u) : ~o;
    return __uint_as_float(b);
}

__global__ __launch_bounds__(256) void persist_kernel(
    const int* __restrict__ edges,
    const float* __restrict__ w_phi0, const float* __restrict__ b_phi0,
    const float* __restrict__ w_phi1, const float* __restrict__ b_phi1)
{
    __shared__ float gf[NPG];
    __shared__ unsigned long long keys[EPG];
    __shared__ int   euv[EPG];
    __shared__ float ew[EPG];
    __shared__ int   parent[NPG];
    __shared__ float death[NPG];
    __shared__ unsigned char paired[NPG];
    __shared__ unsigned int  cmax[NPG];
    __shared__ float bs[NPG], ds[NPG];

    const int tid  = threadIdx.x;
    const int g    = blockIdx.x;
    const int s    = blockIdx.y;          // 0: sublevel(f), 1: superlevel(-f)
    const float sign = s ? -1.f : 1.f;

    gf[tid]     = sign * g_f[g * NPG + tid];
    parent[tid] = tid;
    death[tid]  = 0.f;
    paired[tid] = 0;
    cmax[tid]   = 0u;
    __syncthreads();

    // edge weights + sort keys (edge index in low bits -> total order;
    // equal-w edge order does not change the death assignment: elder rule)
    #pragma unroll
    for (int r = 0; r < 4; r++) {
        int e = tid + r * 256;
        int u = edges[(size_t)(g * EPG + e) * 2 + 0] & (NPG - 1);
        int v = edges[(size_t)(g * EPG + e) * 2 + 1] & (NPG - 1);
        float w = fmaxf(gf[u], gf[v]);
        euv[e] = (u << 16) | v;
        ew[e]  = w;
        keys[e] = ((unsigned long long)f2ord(w) << 32) | (unsigned int)e;
    }
    __syncthreads();

    // bitonic sort 1024 keys (ascending), 256 threads
    for (int k = 2; k <= EPG; k <<= 1) {
        for (int j = k >> 1; j > 0; j >>= 1) {
            #pragma unroll 2
            for (int i = tid; i < EPG; i += 256) {
                int p = i ^ j;
                if (p > i) {
                    bool up = ((i & k) == 0);
                    unsigned long long a = keys[i], b = keys[p];
                    if ((a > b) == up) { keys[i] = b; keys[p] = a; }
                }
            }
            __syncthreads();
        }
    }

    // serial union-find scan (elder rule), thread 0
    if (tid == 0) {
        for (int t = 0; t < EPG; t++) {
            int e  = (int)(keys[t] & 0xFFFFFFFFu);
            int uv = euv[e];
            int u  = uv >> 16, v = uv & 0xFFFF;
            int ru = u; while (parent[ru] != ru) ru = parent[ru];
            int rv = v; while (parent[rv] != rv) rv = parent[rv];
            parent[u] = ru; parent[v] = rv;     // endpoint path compression
            if (ru != rv) {
                float fu = gf[ru], fv = gf[rv];
                bool ue    = (fu < fv) || (fu == fv && ru < rv);
                int elder  = ue ? ru : rv;
                int young  = ue ? rv : ru;
                parent[young] = elder;
                death[young]  = ew[e];
                paired[young] = 1;
            }
        }
    }
    __syncthreads();

    // full path compression by pointer jumping (8 rounds cover depth<=256)
    #pragma unroll
    for (int it = 0; it < 8; it++) {
        int p = parent[parent[tid]];
        __syncthreads();
        parent[tid] = p;
        __syncthreads();
    }

    // component max of filtration (essential-class deaths). atomicMax of an
    // order-preserving uint transform: order-independent -> deterministic.
    atomicMax(&cmax[parent[tid]], f2ord(gf[tid]));
    __syncthreads();

    float dv = paired[tid] ? death[tid] : ord2f(cmax[parent[tid]]);
    if (s == 0) { bs[tid] = gf[tid]; ds[tid] = dv;       }  // h0 = (f, d_sub)
    else        { bs[tid] = -dv;     ds[tid] = -gf[tid]; }  // h1 = (-d_sup, f)
    __syncthreads();

    // fused phi-MLP + per-graph sum pooling: one thread per channel
    const float* wp = s ? w_phi1 : w_phi0;
    const float* bp = s ? b_phi1 : b_phi0;
    float wb = wp[tid], wd = wp[HP + tid], bb = bp[tid];
    float acc = 0.f;
    #pragma unroll 4
    for (int v = 0; v < NPG; v++)
        acc += fmaxf(bs[v] * wb + ds[v] * wd + bb, 0.f);
    g_pool[s][g][tid] = acc;
}

// ---------------------------------------------------------------------------
// Kernel 3: head — out[g,c] = concat(p0,p1)[g] . w_head[:,c] + b_head[c]
// ---------------------------------------------------------------------------
__global__ void head_kernel(const float* __restrict__ w_head,
                            const float* __restrict__ b_head,
                            float* __restrict__ out)
{
    int g = blockIdx.x;
    int warp = threadIdx.x >> 5, lane = threadIdx.x & 31;
    if (warp >= NC) return;
    const float* p0 = g_pool[0][g];
    const float* p1 = g_pool[1][g];
    float acc = 0.f;
    #pragma unroll
    for (int k = lane; k < HP; k += 32) {
        acc += p0[k] * w_head[k * NC + warp];
        acc += p1[k] * w_head[(HP + k) * NC + warp];
    }
    #pragma unroll
    for (int o = 16; o > 0; o >>= 1) acc += __shfl_down_sync(0xFFFFFFFFu, acc, o);
    if (lane == 0) out[g * NC + warp] = acc + b_head[warp];
}

// ---------------------------------------------------------------------------
extern "C" void kernel_launch(void* const* d_in, const int* in_sizes, int n_in,
                              void* d_out, int out_size)
{
    const float* x   = (const float*)d_in[0];
    const int*   edges = (const int*)d_in[1];
    // d_in[2] = sample_id (layout known, unused)
    const float* w1  = (const float*)d_in[3];
    const float* b1  = (const float*)d_in[4];
    const float* w2  = (const float*)d_in[5];
    const float* b2  = (const float*)d_in[6];
    const float* wp0 = (const float*)d_in[7];
    const float* bp0 = (const float*)d_in[8];
    const float* wp1 = (const float*)d_in[9];
    const float* bp1 = (const float*)d_in[10];
    const float* wh  = (const float*)d_in[11];
    const float* bh  = (const float*)d_in[12];

    filt_kernel<<<NN / MT, 256>>>(x, w1, b1, w2, b2);
    persist_kernel<<<dim3(NG, 2), 256>>>(edges, wp0, bp0, wp1, bp1);
    head_kernel<<<NG, 320>>>(wh, bh, (float*)d_out);
}

// round 5
// speedup vs baseline: 1.8215x; 1.8215x over previous
#include <cuda_runtime.h>
#include <cstdint>

#define NG   64      // graphs
#define NPG  256     // nodes per graph
#define EPG  1024    // edges per graph
#define NN   (NG*NPG)
#define DF   512
#define HF   1024
#define HP   256
#define NC   10

__device__ float g_f[NN];
__device__ float g_pool[2][NG][HP];

__device__ __forceinline__ uint32_t f2tf32(float f) {
    uint32_t r;
    asm("cvt.rna.tf32.f32 %0, %1;" : "=r"(r) : "f"(f));
    return r;
}

// ---------------------------------------------------------------------------
// Kernel 1: fused filtration via tf32 tensor-core GEMM
//   f[n] = sigmoid( sum_c relu( x[n].W1[:,c] + b1[c] ) * w2[c] + b2 )
// CTA: 64 rows x 128-channel tile (loop ct over 8 tiles), K chunks of 32.
// 8 warps as 2(M) x 4(N); warp tile 32x32 via m16n8k8 tf32 mma.
// h [16384,1024] never materialized.
// ---------------------------------------------------------------------------
#define MT    64
#define CTW   128
#define KC    32
#define WSTR  136   // ws row stride (mod 32 == 8 -> conflict-free B frags)

__global__ __launch_bounds__(256, 2) void filt_kernel(
    const float* __restrict__ x,  const float* __restrict__ w1,
    const float* __restrict__ b1, const float* __restrict__ w2,
    const float* __restrict__ b2)
{
    __shared__ uint32_t xs[MT][KC];      // XOR-swizzled: col ^ (4*(row&7))
    __shared__ uint32_t ws[KC][WSTR];    // k-major W tile, padded stride
    __shared__ float    red[MT][4];      // per-warp-column row partials

    const int tid  = threadIdx.x;
    const int lane = tid & 31;
    const int warp = tid >> 5;
    const int wm   = warp >> 2;          // 0..1  (M)
    const int wn   = warp & 3;           // 0..3  (N)
    const int g    = lane >> 2;          // 0..7
    const int t4   = lane & 3;           // 0..3
    const int rowbase = blockIdx.x * MT;

    float facc = 0.f;                    // per-thread (tid<64) row accumulator

    for (int ct = 0; ct < HF; ct += CTW) {
        float c[2][4][4];
        #pragma unroll
        for (int mt = 0; mt < 2; mt++)
            #pragma unroll
            for (int nt = 0; nt < 4; nt++)
                #pragma unroll
                for (int j = 0; j < 4; j++) c[mt][nt][j] = 0.f;

        for (int k0 = 0; k0 < DF; k0 += KC) {
            __syncthreads();
            // X tile: 64 rows x 32 k (512 float4, 2/thread), swizzled store
            #pragma unroll
            for (int r = 0; r < 2; r++) {
                int idx = tid + r * 256;
                int m   = idx >> 3;
                int kq  = idx & 7;
                float4 v = *(const float4*)&x[(size_t)(rowbase + m) * DF + k0 + kq * 4];
                uint4 t; t.x = f2tf32(v.x); t.y = f2tf32(v.y);
                         t.z = f2tf32(v.z); t.w = f2tf32(v.w);
                int swc = (kq * 4) ^ ((m & 7) * 4);
                *(uint4*)&xs[m][swc] = t;
            }
            // W tile: 32 k x 128 c (1024 float4, 4/thread)
            #pragma unroll
            for (int r = 0; r < 4; r++) {
                int idx = tid + r * 256;
                int kk  = idx >> 5;
                int nq  = idx & 31;
                float4 v = *(const float4*)&w1[(size_t)(k0 + kk) * HF + ct + nq * 4];
                uint4 t; t.x = f2tf32(v.x); t.y = f2tf32(v.y);
                         t.z = f2tf32(v.z); t.w = f2tf32(v.w);
                *(uint4*)&ws[kk][nq * 4] = t;
            }
            __syncthreads();

            #pragma unroll
            for (int ks = 0; ks < KC; ks += 8) {
                uint32_t a[2][4], b[4][2];
                #pragma unroll
                for (int mt = 0; mt < 2; mt++) {
                    int r0 = wm * 32 + mt * 16 + g;   // (r0&7)==g, (r0+8)&7==g
                    int c0 = (ks + t4) ^ (g * 4);
                    int c1 = (ks + t4 + 4) ^ (g * 4);
                    a[mt][0] = xs[r0][c0];
                    a[mt][1] = xs[r0 + 8][c0];
                    a[mt][2] = xs[r0][c1];
                    a[mt][3] = xs[r0 + 8][c1];
                }
                #pragma unroll
                for (int nt = 0; nt < 4; nt++) {
                    int n = wn * 32 + nt * 8 + g;
                    b[nt][0] = ws[ks + t4][n];
                    b[nt][1] = ws[ks + t4 + 4][n];
                }
                #pragma unroll
                for (int mt = 0; mt < 2; mt++)
                    #pragma unroll
                    for (int nt = 0; nt < 4; nt++)
                        asm volatile(
                            "mma.sync.aligned.m16n8k8.row.col.f32.tf32.tf32.f32 "
                            "{%0,%1,%2,%3}, {%4,%5,%6,%7}, {%8,%9}, {%0,%1,%2,%3};"
                            : "+f"(c[mt][nt][0]), "+f"(c[mt][nt][1]),
                              "+f"(c[mt][nt][2]), "+f"(c[mt][nt][3])
                            : "r"(a[mt][0]), "r"(a[mt][1]), "r"(a[mt][2]), "r"(a[mt][3]),
                              "r"(b[nt][0]), "r"(b[nt][1]));
            }
        }

        // epilogue: relu + w2-weighted channel reduction for this tile
        #pragma unroll
        for (int mt = 0; mt < 2; mt++) {
            float s_lo = 0.f, s_hi = 0.f;   // rows g, g+8
            #pragma unroll
            for (int nt = 0; nt < 4; nt++) {
                int col = ct + wn * 32 + nt * 8 + 2 * t4;
                float bb0 = __ldg(&b1[col]),   bb1 = __ldg(&b1[col + 1]);
                float w20 = __ldg(&w2[col]),   w21 = __ldg(&w2[col + 1]);
                s_lo += fmaxf(c[mt][nt][0] + bb0, 0.f) * w20
                      + fmaxf(c[mt][nt][1] + bb1, 0.f) * w21;
                s_hi += fmaxf(c[mt][nt][2] + bb0, 0.f) * w20
                      + fmaxf(c[mt][nt][3] + bb1, 0.f) * w21;
            }
            // butterfly over the t4 quad (fixed order -> deterministic)
            s_lo += __shfl_xor_sync(0xFFFFFFFFu, s_lo, 1);
            s_lo += __shfl_xor_sync(0xFFFFFFFFu, s_lo, 2);
            s_hi += __shfl_xor_sync(0xFFFFFFFFu, s_hi, 1);
            s_hi += __shfl_xor_sync(0xFFFFFFFFu, s_hi, 2);
            if (t4 == 0) {
                int r0 = wm * 32 + mt * 16 + g;
                red[r0][wn]     = s_lo;
                red[r0 + 8][wn] = s_hi;
            }
        }
        __syncthreads();
        if (tid < MT)
            facc += red[tid][0] + red[tid][1] + red[tid][2] + red[tid][3];
        __syncthreads();
    }

    if (tid < MT) {
        float t = facc + b2[0];
        g_f[rowbase + tid] = 1.f / (1.f + expf(-t));
    }
}

// ---------------------------------------------------------------------------
// Kernel 2: per-(graph, sign) 0-dim persistence + fused phi-MLP pooling.
// One CTA per (graph, filtration sign). All state in smem.
// ---------------------------------------------------------------------------
__device__ __forceinline__ unsigned int f2ord(float f) {
    unsigned int b = __float_as_uint(f);
    return b ^ (((int)b >> 31) | 0x80000000u);
}
__device__ __forceinline__ float ord2f(unsigned int o) {
    unsigned int b = (o & 0x80000000u) ? (o ^ 0x80000000u) : ~o;
    return __uint_as_float(b);
}

__global__ __launch_bounds__(256) void persist_kernel(
    const int* __restrict__ edges,
    const float* __restrict__ w_phi0, const float* __restrict__ b_phi0,
    const float* __restrict__ w_phi1, const float* __restrict__ b_phi1)
{
    __shared__ float gf[NPG];
    __shared__ unsigned long long keys[EPG];
    __shared__ int   euv[EPG];
    __shared__ float ew[EPG];
    __shared__ int   parent[NPG];
    __shared__ float death[NPG];
    __shared__ unsigned char paired[NPG];
    __shared__ unsigned int  cmax[NPG];
    __shared__ float bs[NPG], ds[NPG];

    const int tid  = threadIdx.x;
    const int g    = blockIdx.x;
    const int s    = blockIdx.y;          // 0: sublevel(f), 1: superlevel(-f)
    const float sign = s ? -1.f : 1.f;

    gf[tid]     = sign * g_f[g * NPG + tid];
    parent[tid] = tid;
    death[tid]  = 0.f;
    paired[tid] = 0;
    cmax[tid]   = 0u;
    __syncthreads();

    // edge weights + sort keys (edge index in low bits -> total order;
    // equal-w edge order does not change the death assignment: elder rule)
    #pragma unroll
    for (int r = 0; r < 4; r++) {
        int e = tid + r * 256;
        int u = edges[(size_t)(g * EPG + e) * 2 + 0] & (NPG - 1);
        int v = edges[(size_t)(g * EPG + e) * 2 + 1] & (NPG - 1);
        float w = fmaxf(gf[u], gf[v]);
        euv[e] = (u << 16) | v;
        ew[e]  = w;
        keys[e] = ((unsigned long long)f2ord(w) << 32) | (unsigned int)e;
    }
    __syncthreads();

    // bitonic sort 1024 keys (ascending), 256 threads
    for (int k = 2; k <= EPG; k <<= 1) {
        for (int j = k >> 1; j > 0; j >>= 1) {
            #pragma unroll 2
            for (int i = tid; i < EPG; i += 256) {
                int p = i ^ j;
                if (p > i) {
                    bool up = ((i & k) == 0);
                    unsigned long long a = keys[i], b = keys[p];
                    if ((a > b) == up) { keys[i] = b; keys[p] = a; }
                }
            }
            __syncthreads();
        }
    }

    // serial union-find scan (elder rule), thread 0.
    // Early break: after NPG-1 merges everything is one component and every
    // remaining edge is a guaranteed no-op.
    if (tid == 0) {
        int merges = 0;
        for (int t = 0; t < EPG; t++) {
            int e  = (int)(keys[t] & 0xFFFFFFFFu);
            int uv = euv[e];
            int u  = uv >> 16, v = uv & 0xFFFF;
            int ru = u; while (parent[ru] != ru) ru = parent[ru];
            int rv = v; while (parent[rv] != rv) rv = parent[rv];
            parent[u] = ru; parent[v] = rv;     // endpoint path compression
            if (ru != rv) {
                float fu = gf[ru], fv = gf[rv];
                bool ue    = (fu < fv) || (fu == fv && ru < rv);
                int elder  = ue ? ru : rv;
                int young  = ue ? rv : ru;
                parent[young] = elder;
                death[young]  = ew[e];
                paired[young] = 1;
                if (++merges == NPG - 1) break;
            }
        }
    }
    __syncthreads();

    // full path compression by pointer jumping (8 rounds cover depth<=256)
    #pragma unroll
    for (int it = 0; it < 8; it++) {
        int p = parent[parent[tid]];
        __syncthreads();
        parent[tid] = p;
        __syncthreads();
    }

    // component max of filtration (essential-class deaths). atomicMax of an
    // order-preserving uint transform: order-independent -> deterministic.
    atomicMax(&cmax[parent[tid]], f2ord(gf[tid]));
    __syncthreads();

    float dv = paired[tid] ? death[tid] : ord2f(cmax[parent[tid]]);
    if (s == 0) { bs[tid] = gf[tid]; ds[tid] = dv;       }  // h0 = (f, d_sub)
    else        { bs[tid] = -dv;     ds[tid] = -gf[tid]; }  // h1 = (-d_sup, f)
    __syncthreads();

    // fused phi-MLP + per-graph sum pooling: one thread per channel
    const float* wp = s ? w_phi1 : w_phi0;
    const float* bp = s ? b_phi1 : b_phi0;
    float wb = wp[tid], wd = wp[HP + tid], bb = bp[tid];
    float acc = 0.f;
    #pragma unroll 4
    for (int v = 0; v < NPG; v++)
        acc += fmaxf(bs[v] * wb + ds[v] * wd + bb, 0.f);
    g_pool[s][g][tid] = acc;
}

// ---------------------------------------------------------------------------
// Kernel 3: head — out[g,c] = concat(p0,p1)[g] . w_head[:,c] + b_head[c]
// ---------------------------------------------------------------------------
__global__ void head_kernel(const float* __restrict__ w_head,
                            const float* __restrict__ b_head,
                            float* __restrict__ out)
{
    int g = blockIdx.x;
    int warp = threadIdx.x >> 5, lane = threadIdx.x & 31;
    if (warp >= NC) return;
    const float* p0 = g_pool[0][g];
    const float* p1 = g_pool[1][g];
    float acc = 0.f;
    #pragma unroll
    for (int k = lane; k < HP; k += 32) {
        acc += p0[k] * w_head[k * NC + warp];
        acc += p1[k] * w_head[(HP + k) * NC + warp];
    }
    #pragma unroll
    for (int o = 16; o > 0; o >>= 1) acc += __shfl_down_sync(0xFFFFFFFFu, acc, o);
    if (lane == 0) out[g * NC + warp] = acc + b_head[warp];
}

// ---------------------------------------------------------------------------
extern "C" void kernel_launch(void* const* d_in, const int* in_sizes, int n_in,
                              void* d_out, int out_size)
{
    const float* x   = (const float*)d_in[0];
    const int*   edges = (const int*)d_in[1];
    // d_in[2] = sample_id (layout known, unused)
    const float* w1  = (const float*)d_in[3];
    const float* b1  = (const float*)d_in[4];
    const float* w2  = (const float*)d_in[5];
    const float* b2  = (const float*)d_in[6];
    const float* wp0 = (const float*)d_in[7];
    const float* bp0 = (const float*)d_in[8];
    const float* wp1 = (const float*)d_in[9];
    const float* bp1 = (const float*)d_in[10];
    const float* wh  = (const float*)d_in[11];
    const float* bh  = (const float*)d_in[12];

    filt_kernel<<<NN / MT, 256>>>(x, w1, b1, w2, b2);
    persist_kernel<<<dim3(NG, 2), 256>>>(edges, wp0, bp0, wp1, bp1);
    head_kernel<<<NG, 320>>>(wh, bh, (float*)d_out);
}

// round 7
// speedup vs baseline: 3.1171x; 1.7113x over previous
#include <cuda_runtime.h>
#include <cstdint>

#define NG   64
#define NPG  256
#define EPG  1024
#define NN   (NG*NPG)
#define DF   512
#define HF   1024
#define HP   256
#define NC   10

__device__ float g_f[NN];
__device__ float g_pool[2][NG][HP];

// ---------------------------------------------------------------------------
// Kernel 1: fused filtration via tf32 mma, 3-stage cp.async pipeline.
//   f[n] = sigmoid( sum_c relu( x[n].W1[:,c] + b1[c] ) * w2[c] + b2 )
// CTA: 64 rows; loop over 8 tiles of 128 channels; K chunks of 32.
// 8 warps = 2(M) x 4(N), warp tile 32x32, m16n8k8 tf32 (raw fp32 bits:
// hardware truncates to tf32 -> no cvt ALU work).
// ---------------------------------------------------------------------------
#define MT    64
#define CTW   128
#define KC    32
#define WSTR  136                       // mod 32 == 8 -> conflict-free B frags
#define NCHUNK 128                      // (HF/CTW) * (DF/KC) = 8 * 16
#define STAGE_X_WORDS (MT*KC)           // 2048
#define STAGE_W_WORDS (KC*WSTR)         // 4352
#define STAGE_WORDS   (STAGE_X_WORDS + STAGE_W_WORDS)   // 6400
#define NSTAGE 3
#define RED_OFF_WORDS (NSTAGE*STAGE_WORDS)              // 19200
#define FILT_SMEM_BYTES ((RED_OFF_WORDS + MT*4) * 4)    // 77824

__device__ __forceinline__ void filt_issue_chunk(
    const float* __restrict__ x, const float* __restrict__ w1,
    int rowbase, int tid, uint32_t sbase, int chunk)
{
    const int st = chunk % NSTAGE;
    const int ct = (chunk >> 4) * CTW;
    const int k0 = (chunk & 15) * KC;
    uint32_t xb = sbase + st * (STAGE_WORDS * 4);
    #pragma unroll
    for (int r = 0; r < 2; r++) {                 // X tile: 64x32 f32, swizzled
        int idx = tid + r * 256;
        int m   = idx >> 3;
        int kq  = idx & 7;
        uint32_t dst = xb + (uint32_t)(m * KC + ((kq * 4) ^ ((m & 7) * 4))) * 4;
        const float* src = &x[(size_t)(rowbase + m) * DF + k0 + kq * 4];
        asm volatile("cp.async.cg.shared.global [%0], [%1], 16;" :: "r"(dst), "l"(src));
    }
    uint32_t wb = xb + STAGE_X_WORDS * 4;
    #pragma unroll
    for (int r = 0; r < 4; r++) {                 // W tile: 32x128 f32, padded
        int idx = tid + r * 256;
        int kk  = idx >> 5;
        int nq  = idx & 31;
        uint32_t dst = wb + (uint32_t)(kk * WSTR + nq * 4) * 4;
        const float* src = &w1[(size_t)(k0 + kk) * HF + ct + nq * 4];
        asm volatile("cp.async.cg.shared.global [%0], [%1], 16;" :: "r"(dst), "l"(src));
    }
    asm volatile("cp.async.commit_group;");
}

__global__ __launch_bounds__(256, 2) void filt_kernel(
    const float* __restrict__ x,  const float* __restrict__ w1,
    const float* __restrict__ b1, const float* __restrict__ w2,
    const float* __restrict__ b2)
{
    extern __shared__ uint32_t smem[];
    uint32_t sbase = (uint32_t)__cvta_generic_to_shared(smem);

    const int tid  = threadIdx.x;
    const int lane = tid & 31;
    const int warp = tid >> 5;
    const int wm   = warp >> 2;
    const int wn   = warp & 3;
    const int g    = lane >> 2;
    const int t4   = lane & 3;
    const int rowbase = blockIdx.x * MT;

    filt_issue_chunk(x, w1, rowbase, tid, sbase, 0);
    filt_issue_chunk(x, w1, rowbase, tid, sbase, 1);

    float c[2][4][4];
    float facc_lo[2] = {0.f, 0.f}, facc_hi[2] = {0.f, 0.f};

    for (int chunk = 0; chunk < NCHUNK; chunk++) {
        if ((chunk & 15) == 0) {
            #pragma unroll
            for (int mt = 0; mt < 2; mt++)
                #pragma unroll
                for (int nt = 0; nt < 4; nt++)
                    #pragma unroll
                    for (int j = 0; j < 4; j++) c[mt][nt][j] = 0.f;
        }
        if (chunk < NCHUNK - 1) asm volatile("cp.async.wait_group 1;");
        else                    asm volatile("cp.async.wait_group 0;");
        __syncthreads();                       // stage ready + prev reads done
        if (chunk + 2 < NCHUNK)
            filt_issue_chunk(x, w1, rowbase, tid, sbase, chunk + 2);

        const uint32_t* xs = smem + (chunk % NSTAGE) * STAGE_WORDS;
        const uint32_t* ws = xs + STAGE_X_WORDS;

        #pragma unroll
        for (int ks = 0; ks < KC; ks += 8) {
            uint32_t a[2][4], b[4][2];
            #pragma unroll
            for (int mt = 0; mt < 2; mt++) {
                int r0 = wm * 32 + mt * 16 + g;
                int c0 = (ks + t4) ^ (g * 4);
                int c1 = (ks + t4 + 4) ^ (g * 4);
                a[mt][0] = xs[r0 * KC + c0];
                a[mt][1] = xs[(r0 + 8) * KC + c0];
                a[mt][2] = xs[r0 * KC + c1];
                a[mt][3] = xs[(r0 + 8) * KC + c1];
            }
            #pragma unroll
            for (int nt = 0; nt < 4; nt++) {
                int n = wn * 32 + nt * 8 + g;
                b[nt][0] = ws[(ks + t4) * WSTR + n];
                b[nt][1] = ws[(ks + t4 + 4) * WSTR + n];
            }
            #pragma unroll
            for (int mt = 0; mt < 2; mt++)
                #pragma unroll
                for (int nt = 0; nt < 4; nt++)
                    asm volatile(
                        "mma.sync.aligned.m16n8k8.row.col.f32.tf32.tf32.f32 "
                        "{%0,%1,%2,%3}, {%4,%5,%6,%7}, {%8,%9}, {%0,%1,%2,%3};"
                        : "+f"(c[mt][nt][0]), "+f"(c[mt][nt][1]),
                          "+f"(c[mt][nt][2]), "+f"(c[mt][nt][3])
                        : "r"(a[mt][0]), "r"(a[mt][1]), "r"(a[mt][2]), "r"(a[mt][3]),
                          "r"(b[nt][0]), "r"(b[nt][1]));
        }

        if ((chunk & 15) == 15) {              // tile epilogue, registers only
            int ct = (chunk >> 4) * CTW;
            #pragma unroll
            for (int mt = 0; mt < 2; mt++) {
                float s_lo = 0.f, s_hi = 0.f;
                #pragma unroll
                for (int nt = 0; nt < 4; nt++) {
                    int col = ct + wn * 32 + nt * 8 + 2 * t4;
                    float bb0 = __ldg(&b1[col]),   bb1 = __ldg(&b1[col + 1]);
                    float w20 = __ldg(&w2[col]),   w21 = __ldg(&w2[col + 1]);
                    s_lo += fmaxf(c[mt][nt][0] + bb0, 0.f) * w20
                          + fmaxf(c[mt][nt][1] + bb1, 0.f) * w21;
                    s_hi += fmaxf(c[mt][nt][2] + bb0, 0.f) * w20
                          + fmaxf(c[mt][nt][3] + bb1, 0.f) * w21;
                }
                facc_lo[mt] += s_lo;
                facc_hi[mt] += s_hi;
            }
        }
    }

    float (*red)[4] = (float (*)[4])(smem + RED_OFF_WORDS);
    #pragma unroll
    for (int mt = 0; mt < 2; mt++) {
        float slo = facc_lo[mt], shi = facc_hi[mt];
        slo += __shfl_xor_sync(0xFFFFFFFFu, slo, 1);
        slo += __shfl_xor_sync(0xFFFFFFFFu, slo, 2);
        shi += __shfl_xor_sync(0xFFFFFFFFu, shi, 1);
        shi += __shfl_xor_sync(0xFFFFFFFFu, shi, 2);
        if (t4 == 0) {
            int r0 = wm * 32 + mt * 16 + g;
            red[r0][wn]     = slo;
            red[r0 + 8][wn] = shi;
        }
    }
    __syncthreads();
    if (tid < MT) {
        float t = red[tid][0] + red[tid][1] + red[tid][2] + red[tid][3] + b2[0];
        g_f[rowbase + tid] = 1.f / (1.f + expf(-t));
    }
}

// ---------------------------------------------------------------------------
// Kernel 2: per-(graph, sign) persistence.
// Boruvka MSF (parallel, smem) -> sort <=255 MST edges -> serial elder-rule
// Kruskal over MST edges only (identical deaths: non-MST edges never merge
// under the globally-unique key order). Fused phi-MLP pooling.
// ---------------------------------------------------------------------------
__device__ __forceinline__ unsigned int f2ord(float f) {
    unsigned int b = __float_as_uint(f);
    return b ^ (((int)b >> 31) | 0x80000000u);
}
__device__ __forceinline__ float ord2f(unsigned int o) {
    unsigned int b = (o & 0x80000000u) ? (o ^ 0x80000000u) : ~o;
    return __uint_as_float(b);
}

__global__ __launch_bounds__(256) void persist_kernel(
    const int* __restrict__ edges,
    const float* __restrict__ w_phi0, const float* __restrict__ b_phi0,
    const float* __restrict__ w_phi1, const float* __restrict__ b_phi1)
{
    __shared__ float gf[NPG];
    __shared__ int   euv[EPG];
    __shared__ float ew[EPG];
    __shared__ unsigned long long ekey[EPG];
    __shared__ unsigned long long minE[NPG];
    __shared__ int   parent[NPG];
    __shared__ int   parent2[NPG];
    __shared__ unsigned char mst[EPG];
    __shared__ unsigned long long mlist[NPG];
    __shared__ float death[NPG];
    __shared__ unsigned char paired[NPG];
    __shared__ unsigned int  cmax[NPG];
    __shared__ float bs[NPG], ds[NPG];
    __shared__ int sh_changed, sh_nf, sh_cnt;

    const int tid = threadIdx.x;
    const int g   = blockIdx.x;
    const int s   = blockIdx.y;
    const float sign = s ? -1.f : 1.f;

    gf[tid]     = sign * g_f[g * NPG + tid];
    parent[tid] = tid;
    death[tid]  = 0.f;
    paired[tid] = 0;
    cmax[tid]   = 0u;
    __syncthreads();

    #pragma unroll
    for (int r = 0; r < 4; r++) {
        int e = tid + r * 256;
        int u = edges[(size_t)(g * EPG + e) * 2 + 0] & (NPG - 1);
        int v = edges[(size_t)(g * EPG + e) * 2 + 1] & (NPG - 1);
        float w = fmaxf(gf[u], gf[v]);
        euv[e]  = (u << 16) | v;
        ew[e]   = w;
        ekey[e] = ((unsigned long long)f2ord(w) << 32) | (unsigned int)e;
        mst[e]  = 0;
    }
    __syncthreads();

    // ---- Boruvka MSF: components at least halve each round -> <=8 rounds ----
    for (int round = 0; round < 10; round++) {
        minE[tid] = ~0ull;
        if (tid == 0) sh_changed = 0;
        __syncthreads();

        // min outgoing edge per component root (parent is flat here)
        #pragma unroll
        for (int r = 0; r < 4; r++) {
            int e  = tid + r * 256;
            int uv = euv[e];
            int ru = parent[uv >> 16], rv = parent[uv & 0xFFFF];
            if (ru != rv) {
                unsigned long long k = ekey[e];
                atomicMin(&minE[ru], k);
                atomicMin(&minE[rv], k);
            }
        }
        parent2[tid] = parent[tid];            // snapshot for link phase
        __syncthreads();

        // link phase: roots hook onto their min-edge partner (snapshot reads)
        if (parent2[tid] == tid) {
            unsigned long long mk = minE[tid];
            if (mk != ~0ull) {
                int e  = (int)(mk & 0xFFFFFFFFu);
                int uv = euv[e];
                int ru = parent2[uv >> 16], rv = parent2[uv & 0xFFFF];
                int other = (ru == tid) ? rv : ru;
                // break mutual-pair 2-cycle: smaller root id yields
                if (!((minE[other] == mk) && (other < tid))) {
                    parent[tid] = other;
                    mst[e] = 1;
                    sh_changed = 1;
                }
            }
        }
        __syncthreads();
        if (!sh_changed) break;

        // flatten (pointer jumping until stable)
        for (;;) {
            int pp = parent[tid];
            int p  = parent[pp];
            if (tid == 0) sh_nf = 0;
            __syncthreads();
            parent[tid] = p;
            if (p != pp) sh_nf = 1;
            __syncthreads();
            if (!sh_nf) break;
        }
    }

    // ---- compact MST edges, sort by key (unique keys -> deterministic) ----
    if (tid == 0) sh_cnt = 0;
    __syncthreads();
    #pragma unroll
    for (int r = 0; r < 4; r++) {
        int e = tid + r * 256;
        if (mst[e]) mlist[atomicAdd(&sh_cnt, 1)] = ekey[e];
    }
    __syncthreads();
    const int cnt = sh_cnt;                    // <= 255
    if (tid >= cnt) mlist[tid] = ~0ull;
    parent[tid] = tid;                         // reset for Kruskal
    __syncthreads();

    for (int k = 2; k <= NPG; k <<= 1) {
        for (int j = k >> 1; j > 0; j >>= 1) {
            int p = tid ^ j;
            if (p > tid) {
                bool up = ((tid & k) == 0);
                unsigned long long a = mlist[tid], b = mlist[p];
                if ((a > b) == up) { mlist[tid] = b; mlist[p] = a; }
            }
            __syncthreads();
        }
    }

    // ---- serial elder-rule Kruskal over MST edges (every edge merges) ----
    if (tid == 0) {
        for (int t = 0; t < cnt; t++) {
            int e  = (int)(mlist[t] & 0xFFFFFFFFu);
            int uv = euv[e];
            int u  = uv >> 16, v = uv & 0xFFFF;
            int ru = u, rv = v;
            for (;;) {                         // interleaved dual find (ILP)
                int pu = parent[ru], pv = parent[rv];
                if (pu == ru && pv == rv) break;
                ru = pu; rv = pv;
            }
            parent[u] = ru; parent[v] = rv;    // endpoint compression
            float fu = gf[ru], fv = gf[rv];
            bool ue   = (fu < fv) || (fu == fv && ru < rv);
            int elder = ue ? ru : rv;
            int young = ue ? rv : ru;
            parent[young] = elder;
            death[young]  = ew[e];
            paired[young] = 1;
        }
    }
    __syncthreads();

    // full compression (8 doubling rounds cover depth <= 256)
    #pragma unroll
    for (int it = 0; it < 8; it++) {
        int p = parent[parent[tid]];
        __syncthreads();
        parent[tid] = p;
        __syncthreads();
    }

    atomicMax(&cmax[parent[tid]], f2ord(gf[tid]));
    __syncthreads();

    float dv = paired[tid] ? death[tid] : ord2f(cmax[parent[tid]]);
    if (s == 0) { bs[tid] = gf[tid]; ds[tid] = dv;       }
    else        { bs[tid] = -dv;     ds[tid] = -gf[tid]; }
    __syncthreads();

    const float* wp = s ? w_phi1 : w_phi0;
    const float* bp = s ? b_phi1 : b_phi0;
    float wb = wp[tid], wd = wp[HP + tid], bb = bp[tid];
    float acc = 0.f;
    #pragma unroll 4
    for (int v = 0; v < NPG; v++)
        acc += fmaxf(bs[v] * wb + ds[v] * wd + bb, 0.f);
    g_pool[s][g][tid] = acc;
}

// ---------------------------------------------------------------------------
// Kernel 3: head
// ---------------------------------------------------------------------------
__global__ void head_kernel(const float* __restrict__ w_head,
                            const float* __restrict__ b_head,
                            float* __restrict__ out)
{
    int g = blockIdx.x;
    int warp = threadIdx.x >> 5, lane = threadIdx.x & 31;
    if (warp >= NC) return;
    const float* p0 = g_pool[0][g];
    const float* p1 = g_pool[1][g];
    float acc = 0.f;
    #pragma unroll
    for (int k = lane; k < HP; k += 32) {
        acc += p0[k] * w_head[k * NC + warp];
        acc += p1[k] * w_head[(HP + k) * NC + warp];
    }
    #pragma unroll
    for (int o = 16; o > 0; o >>= 1) acc += __shfl_down_sync(0xFFFFFFFFu, acc, o);
    if (lane == 0) out[g * NC + warp] = acc + b_head[warp];
}

// ---------------------------------------------------------------------------
extern "C" void kernel_launch(void* const* d_in, const int* in_sizes, int n_in,
                              void* d_out, int out_size)
{
    const float* x     = (const float*)d_in[0];
    const int*   edges = (const int*)d_in[1];
    const float* w1  = (const float*)d_in[3];
    const float* b1  = (const float*)d_in[4];
    const float* w2  = (const float*)d_in[5];
    const float* b2  = (const float*)d_in[6];
    const float* wp0 = (const float*)d_in[7];
    const float* bp0 = (const float*)d_in[8];
    const float* wp1 = (const float*)d_in[9];
    const float* bp1 = (const float*)d_in[10];
    const float* wh  = (const float*)d_in[11];
    const float* bh  = (const float*)d_in[12];

    cudaFuncSetAttribute(filt_kernel,
                         cudaFuncAttributeMaxDynamicSharedMemorySize,
                         FILT_SMEM_BYTES);
    filt_kernel<<<NN / MT, 256, FILT_SMEM_BYTES>>>(x, w1, b1, w2, b2);
    persist_kernel<<<dim3(NG, 2), 256>>>(edges, wp0, bp0, wp1, bp1);
    head_kernel<<<NG, 320>>>(wh, bh, (float*)d_out);
}

// round 10
// speedup vs baseline: 3.2816x; 1.0528x over previous
#include <cuda_runtime.h>
#include <cstdint>

#define NG   64
#define NPG  256
#define EPG  1024
#define NN   (NG*NPG)
#define DF   512
#define HF   1024
#define HP   256
#define NC   10

__device__ float g_f[NN];
__device__ float g_pool[2][NG][HP];

// ---------------------------------------------------------------------------
// Kernel 1: fused filtration via tf32 mma, 4-stage cp.async pipeline,
// ldmatrix A-fragment loads.
//   f[n] = sigmoid( sum_c relu( x[n].W1[:,c] + b1[c] ) * w2[c] + b2 )
// CTA: 64 rows; 8 tiles of 128 channels; K chunks of 32.
// 8 warps = 2(M) x 4(N), warp tile 32x32, m16n8k8 tf32 (raw fp32 bits:
// hardware truncates to tf32).
// ---------------------------------------------------------------------------
#define MT    64
#define CTW   128
#define KC    32
#define WSTR  136                       // mod 32 == 8 -> conflict-free B frags
#define NCHUNK 128                      // (HF/CTW) * (DF/KC)
#define STAGE_X_WORDS (MT*KC)           // 2048
#define STAGE_W_WORDS (KC*WSTR)         // 4352
#define STAGE_WORDS   (STAGE_X_WORDS + STAGE_W_WORDS)   // 6400
#define NSTAGE 4
#define PFD    3                        // prefetch distance (<= NSTAGE-1)
#define RED_OFF_WORDS (NSTAGE*STAGE_WORDS)
#define FILT_SMEM_BYTES ((RED_OFF_WORDS + MT*4) * 4)    // 103424

__device__ __forceinline__ void filt_issue_chunk(
    const float* __restrict__ x, const float* __restrict__ w1,
    int rowbase, int tid, uint32_t sbase, int chunk)
{
    const int st = chunk & (NSTAGE - 1);
    const int ct = (chunk >> 4) * CTW;
    const int k0 = (chunk & 15) * KC;
    uint32_t xb = sbase + st * (STAGE_WORDS * 4);
    #pragma unroll
    for (int r = 0; r < 2; r++) {                 // X tile: 64x32 f32, swizzled
        int idx = tid + r * 256;
        int m   = idx >> 3;
        int kq  = idx & 7;
        uint32_t dst = xb + (uint32_t)(m * KC + ((kq * 4) ^ ((m & 7) * 4))) * 4;
        const float* src = &x[(size_t)(rowbase + m) * DF + k0 + kq * 4];
        asm volatile("cp.async.cg.shared.global [%0], [%1], 16;" :: "r"(dst), "l"(src));
    }
    uint32_t wb = xb + STAGE_X_WORDS * 4;
    #pragma unroll
    for (int r = 0; r < 4; r++) {                 // W tile: 32x128 f32, padded
        int idx = tid + r * 256;
        int kk  = idx >> 5;
        int nq  = idx & 31;
        uint32_t dst = wb + (uint32_t)(kk * WSTR + nq * 4) * 4;
        const float* src = &w1[(size_t)(k0 + kk) * HF + ct + nq * 4];
        asm volatile("cp.async.cg.shared.global [%0], [%1], 16;" :: "r"(dst), "l"(src));
    }
    asm volatile("cp.async.commit_group;");
}

__global__ __launch_bounds__(256, 2) void filt_kernel(
    const float* __restrict__ x,  const float* __restrict__ w1,
    const float* __restrict__ b1, const float* __restrict__ w2,
    const float* __restrict__ b2)
{
    extern __shared__ uint32_t smem[];
    uint32_t sbase = (uint32_t)__cvta_generic_to_shared(smem);

    const int tid  = threadIdx.x;
    const int lane = tid & 31;
    const int warp = tid >> 5;
    const int wm   = warp >> 2;
    const int wn   = warp & 3;
    const int g    = lane >> 2;
    const int t4   = lane & 3;
    const int rowbase = blockIdx.x * MT;

    // ldmatrix per-lane A addressing (constant across chunks except stage base):
    //   matrix j = lane>>3 : j0/j1 -> rows +0/+8 ; j2/j3 -> colgroup +4
    //   within matrix: row r = lane&7
    // quadrant order matches a0..a3 of m16n8k8 (rows, rows+8, cols+4, both).
    const int aj = lane >> 3;
    const int ar = lane & 7;
    int arow[2], acs[2];
    #pragma unroll
    for (int mt = 0; mt < 2; mt++) {
        int row  = wm * 32 + mt * 16 + ar + ((aj & 1) << 3);
        arow[mt] = row * KC;                     // word offset of row
        acs[mt]  = (((aj >> 1) << 2)) ^ ((row & 7) * 4);   // cg ^ swizzle
    }

    filt_issue_chunk(x, w1, rowbase, tid, sbase, 0);
    filt_issue_chunk(x, w1, rowbase, tid, sbase, 1);
    filt_issue_chunk(x, w1, rowbase, tid, sbase, 2);

    float c[2][4][4];
    float facc_lo[2] = {0.f, 0.f}, facc_hi[2] = {0.f, 0.f};

    for (int chunk = 0; chunk < NCHUNK; chunk++) {
        if ((chunk & 15) == 0) {
            #pragma unroll
            for (int mt = 0; mt < 2; mt++)
                #pragma unroll
                for (int nt = 0; nt < 4; nt++)
                    #pragma unroll
                    for (int j = 0; j < 4; j++) c[mt][nt][j] = 0.f;
        }
        if (chunk < NCHUNK - 2)      asm volatile("cp.async.wait_group 2;");
        else if (chunk == NCHUNK - 2) asm volatile("cp.async.wait_group 1;");
        else                          asm volatile("cp.async.wait_group 0;");
        __syncthreads();                   // stage ready + prior readers done
        if (chunk + PFD < NCHUNK)
            filt_issue_chunk(x, w1, rowbase, tid, sbase, chunk + PFD);

        const uint32_t stage_b = sbase + (chunk & (NSTAGE - 1)) * (STAGE_WORDS * 4);
        const uint32_t* ws = smem + (chunk & (NSTAGE - 1)) * STAGE_WORDS + STAGE_X_WORDS;

        #pragma unroll
        for (int ks = 0; ks < KC; ks += 8) {
            uint32_t a[2][4], b[4][2];
            #pragma unroll
            for (int mt = 0; mt < 2; mt++) {
                uint32_t addr = stage_b + (uint32_t)(arow[mt] + (ks ^ acs[mt])) * 4;
                asm volatile(
                    "ldmatrix.sync.aligned.m8n8.x4.shared.b16 {%0,%1,%2,%3}, [%4];"
                    : "=r"(a[mt][0]), "=r"(a[mt][1]), "=r"(a[mt][2]), "=r"(a[mt][3])
                    : "r"(addr));
            }
            #pragma unroll
            for (int nt = 0; nt < 4; nt++) {
                int n = wn * 32 + nt * 8 + g;
                b[nt][0] = ws[(ks + t4) * WSTR + n];
                b[nt][1] = ws[(ks + t4 + 4) * WSTR + n];
            }
            #pragma unroll
            for (int mt = 0; mt < 2; mt++)
                #pragma unroll
                for (int nt = 0; nt < 4; nt++)
                    asm volatile(
                        "mma.sync.aligned.m16n8k8.row.col.f32.tf32.tf32.f32 "
                        "{%0,%1,%2,%3}, {%4,%5,%6,%7}, {%8,%9}, {%0,%1,%2,%3};"
                        : "+f"(c[mt][nt][0]), "+f"(c[mt][nt][1]),
                          "+f"(c[mt][nt][2]), "+f"(c[mt][nt][3])
                        : "r"(a[mt][0]), "r"(a[mt][1]), "r"(a[mt][2]), "r"(a[mt][3]),
                          "r"(b[nt][0]), "r"(b[nt][1]));
        }

        if ((chunk & 15) == 15) {              // tile epilogue, registers only
            int ct = (chunk >> 4) * CTW;
            #pragma unroll
            for (int mt = 0; mt < 2; mt++) {
                float s_lo = 0.f, s_hi = 0.f;
                #pragma unroll
                for (int nt = 0; nt < 4; nt++) {
                    int col = ct + wn * 32 + nt * 8 + 2 * t4;
                    float bb0 = __ldg(&b1[col]),   bb1 = __ldg(&b1[col + 1]);
                    float w20 = __ldg(&w2[col]),   w21 = __ldg(&w2[col + 1]);
                    s_lo += fmaxf(c[mt][nt][0] + bb0, 0.f) * w20
                          + fmaxf(c[mt][nt][1] + bb1, 0.f) * w21;
                    s_hi += fmaxf(c[mt][nt][2] + bb0, 0.f) * w20
                          + fmaxf(c[mt][nt][3] + bb1, 0.f) * w21;
                }
                facc_lo[mt] += s_lo;
                facc_hi[mt] += s_hi;
            }
        }
    }

    float (*red)[4] = (float (*)[4])(smem + RED_OFF_WORDS);
    #pragma unroll
    for (int mt = 0; mt < 2; mt++) {
        float slo = facc_lo[mt], shi = facc_hi[mt];
        slo += __shfl_xor_sync(0xFFFFFFFFu, slo, 1);
        slo += __shfl_xor_sync(0xFFFFFFFFu, slo, 2);
        shi += __shfl_xor_sync(0xFFFFFFFFu, shi, 1);
        shi += __shfl_xor_sync(0xFFFFFFFFu, shi, 2);
        if (t4 == 0) {
            int r0 = wm * 32 + mt * 16 + g;
            red[r0][wn]     = slo;
            red[r0 + 8][wn] = shi;
        }
    }
    __syncthreads();
    if (tid < MT) {
        float t = red[tid][0] + red[tid][1] + red[tid][2] + red[tid][3] + b2[0];
        g_f[rowbase + tid] = 1.f / (1.f + expf(-t));
    }
}

// ---------------------------------------------------------------------------
// Kernel 2: per-(graph, sign) persistence.
// Boruvka MSF (parallel, smem) -> sort <=255 MST edges -> serial elder-rule
// Kruskal over MST edges only (identical deaths: non-MST edges never merge
// under the globally-unique key order). Fused phi-MLP pooling.
// ---------------------------------------------------------------------------
__device__ __forceinline__ unsigned int f2ord(float f) {
    unsigned int b = __float_as_uint(f);
    return b ^ (((int)b >> 31) | 0x80000000u);
}
__device__ __forceinline__ float ord2f(unsigned int o) {
    unsigned int b = (o & 0x80000000u) ? (o ^ 0x80000000u) : ~o;
    return __uint_as_float(b);
}

__global__ __launch_bounds__(256) void persist_kernel(
    const int* __restrict__ edges,
    const float* __restrict__ w_phi0, const float* __restrict__ b_phi0,
    const float* __restrict__ w_phi1, const float* __restrict__ b_phi1)
{
    __shared__ float gf[NPG];
    __shared__ int   euv[EPG];
    __shared__ float ew[EPG];
    __shared__ unsigned long long ekey[EPG];
    __shared__ unsigned long long minE[NPG];
    __shared__ int   parent[NPG];
    __shared__ int   parent2[NPG];
    __shared__ unsigned char mst[EPG];
    __shared__ unsigned long long mlist[NPG];
    __shared__ float death[NPG];
    __shared__ unsigned char paired[NPG];
    __shared__ unsigned int  cmax[NPG];
    __shared__ float bs[NPG], ds[NPG];
    __shared__ int sh_changed, sh_nf, sh_cnt;

    const int tid = threadIdx.x;
    const int g   = blockIdx.x;
    const int s   = blockIdx.y;
    const float sign = s ? -1.f : 1.f;

    gf[tid]     = sign * g_f[g * NPG + tid];
    parent[tid] = tid;
    death[tid]  = 0.f;
    paired[tid] = 0;
    cmax[tid]   = 0u;
    __syncthreads();

    #pragma unroll
    for (int r = 0; r < 4; r++) {
        int e = tid + r * 256;
        int u = edges[(size_t)(g * EPG + e) * 2 + 0] & (NPG - 1);
        int v = edges[(size_t)(g * EPG + e) * 2 + 1] & (NPG - 1);
        float w = fmaxf(gf[u], gf[v]);
        euv[e]  = (u << 16) | v;
        ew[e]   = w;
        ekey[e] = ((unsigned long long)f2ord(w) << 32) | (unsigned int)e;
        mst[e]  = 0;
    }
    __syncthreads();

    // ---- Boruvka MSF: components at least halve each round ----
    for (int round = 0; round < 10; round++) {
        minE[tid] = ~0ull;
        if (tid == 0) sh_changed = 0;
        __syncthreads();

        #pragma unroll
        for (int r = 0; r < 4; r++) {
            int e  = tid + r * 256;
            int uv = euv[e];
            int ru = parent[uv >> 16], rv = parent[uv & 0xFFFF];
            if (ru != rv) {
                unsigned long long k = ekey[e];
                atomicMin(&minE[ru], k);
                atomicMin(&minE[rv], k);
            }
        }
        parent2[tid] = parent[tid];            // snapshot for link phase
        __syncthreads();

        if (parent2[tid] == tid) {
            unsigned long long mk = minE[tid];
            if (mk != ~0ull) {
                int e  = (int)(mk & 0xFFFFFFFFu);
                int uv = euv[e];
                int ru = parent2[uv >> 16], rv = parent2[uv & 0xFFFF];
                int other = (ru == tid) ? rv : ru;
                // break mutual-pair 2-cycle: smaller root id yields
                if (!((minE[other] == mk) && (other < tid))) {
                    parent[tid] = other;
                    mst[e] = 1;
                    sh_changed = 1;
                }
            }
        }
        __syncthreads();
        if (!sh_changed) break;

        for (;;) {                             // flatten until stable
            int pp = parent[tid];
            int p  = parent[pp];
            if (tid == 0) sh_nf = 0;
            __syncthreads();
            parent[tid] = p;
            if (p != pp) sh_nf = 1;
            __syncthreads();
            if (!sh_nf) break;
        }
    }

    // ---- compact MST edges, sort by key (unique keys -> deterministic) ----
    if (tid == 0) sh_cnt = 0;
    __syncthreads();
    #pragma unroll
    for (int r = 0; r < 4; r++) {
        int e = tid + r * 256;
        if (mst[e]) mlist[atomicAdd(&sh_cnt, 1)] = ekey[e];
    }
    __syncthreads();
    const int cnt = sh_cnt;                    // <= 255
    if (tid >= cnt) mlist[tid] = ~0ull;
    parent[tid] = tid;                         // reset for Kruskal
    __syncthreads();

    for (int k = 2; k <= NPG; k <<= 1) {
        for (int j = k >> 1; j > 0; j >>= 1) {
            int p = tid ^ j;
            if (p > tid) {
                bool up = ((tid & k) == 0);
                unsigned long long a = mlist[tid], b = mlist[p];
                if ((a > b) == up) { mlist[tid] = b; mlist[p] = a; }
            }
            __syncthreads();
        }
    }

    // ---- serial elder-rule Kruskal over MST edges (every edge merges) ----
    if (tid == 0) {
        for (int t = 0; t < cnt; t++) {
            int e  = (int)(mlist[t] & 0xFFFFFFFFu);
            int uv = euv[e];
            int u  = uv >> 16, v = uv & 0xFFFF;
            int ru = u, rv = v;
            for (;;) {                         // interleaved dual find (ILP)
                int pu = parent[ru], pv = parent[rv];
                if (pu == ru && pv == rv) break;
                ru = pu; rv = pv;
            }
            parent[u] = ru; parent[v] = rv;    // endpoint compression
            float fu = gf[ru], fv = gf[rv];
            bool ue   = (fu < fv) || (fu == fv && ru < rv);
            int elder = ue ? ru : rv;
            int young = ue ? rv : ru;
            parent[young] = elder;
            death[young]  = ew[e];
            paired[young] = 1;
        }
    }
    __syncthreads();

    #pragma unroll
    for (int it = 0; it < 8; it++) {           // full compression
        int p = parent[parent[tid]];
        __syncthreads();
        parent[tid] = p;
        __syncthreads();
    }

    atomicMax(&cmax[parent[tid]], f2ord(gf[tid]));
    __syncthreads();

    float dv = paired[tid] ? death[tid] : ord2f(cmax[parent[tid]]);
    if (s == 0) { bs[tid] = gf[tid]; ds[tid] = dv;       }
    else        { bs[tid] = -dv;     ds[tid] = -gf[tid]; }
    __syncthreads();

    const float* wp = s ? w_phi1 : w_phi0;
    const float* bp = s ? b_phi1 : b_phi0;
    float wb = wp[tid], wd = wp[HP + tid], bb = bp[tid];
    float acc = 0.f;
    #pragma unroll 4
    for (int v = 0; v < NPG; v++)
        acc += fmaxf(bs[v] * wb + ds[v] * wd + bb, 0.f);
    g_pool[s][g][tid] = acc;
}

// ---------------------------------------------------------------------------
// Kernel 3: head
// ---------------------------------------------------------------------------
__global__ void head_kernel(const float* __restrict__ w_head,
                            const float* __restrict__ b_head,
                            float* __restrict__ out)
{
    int g = blockIdx.x;
    int warp = threadIdx.x >> 5, lane = threadIdx.x & 31;
    if (warp >= NC) return;
    const float* p0 = g_pool[0][g];
    const float* p1 = g_pool[1][g];
    float acc = 0.f;
    #pragma unroll
    for (int k = lane; k < HP; k += 32) {
        acc += p0[k] * w_head[k * NC + warp];
        acc += p1[k] * w_head[(HP + k) * NC + warp];
    }
    #pragma unroll
    for (int o = 16; o > 0; o >>= 1) acc += __shfl_down_sync(0xFFFFFFFFu, acc, o);
    if (lane == 0) out[g * NC + warp] = acc + b_head[warp];
}

// ---------------------------------------------------------------------------
extern "C" void kernel_launch(void* const* d_in, const int* in_sizes, int n_in,
                              void* d_out, int out_size)
{
    const float* x     = (const float*)d_in[0];
    const int*   edges = (const int*)d_in[1];
    const float* w1  = (const float*)d_in[3];
    const float* b1  = (const float*)d_in[4];
    const float* w2  = (const float*)d_in[5];
    const float* b2  = (const float*)d_in[6];
    const float* wp0 = (const float*)d_in[7];
    const float* bp0 = (const float*)d_in[8];
    const float* wp1 = (const float*)d_in[9];
    const float* bp1 = (const float*)d_in[10];
    const float* wh  = (const float*)d_in[11];
    const float* bh  = (const float*)d_in[12];

    cudaFuncSetAttribute(filt_kernel,
                         cudaFuncAttributeMaxDynamicSharedMemorySize,
                         FILT_SMEM_BYTES);
    filt_kernel<<<NN / MT, 256, FILT_SMEM_BYTES>>>(x, w1, b1, w2, b2);
    persist_kernel<<<dim3(NG, 2), 256>>>(edges, wp0, bp0, wp1, bp1);
    head_kernel<<<NG, 320>>>(wh, bh, (float*)d_out);
}

// round 15
// speedup vs baseline: 4.9325x; 1.5031x over previous
#include <cuda_runtime.h>
#include <cuda_bf16.h>
#include <cstdint>

#define NG   64
#define NPG  256
#define EPG  1024
#define NN   (NG*NPG)
#define DF   512
#define HF   1024
#define HP   256
#define NC   10

__device__ float g_f[NN];
__device__ float g_pool[2][NG][HP];
__device__ __align__(16) __nv_bfloat16 g_xb[(size_t)NN * DF];   // X in bf16
__device__ __align__(16) __nv_bfloat16 g_w1b[(size_t)HF * DF];  // W1^T in bf16

// ---------------------------------------------------------------------------
// Prep: X -> bf16, W1 -> transposed bf16 [HF][DF]
// ---------------------------------------------------------------------------
__global__ void prep_x_kernel(const float4* __restrict__ x4) {
    size_t i = (size_t)blockIdx.x * blockDim.x + threadIdx.x;  // over NN*DF/4
    float4 v = x4[i];
    __nv_bfloat162* dst = (__nv_bfloat162*)g_xb;
    dst[i * 2 + 0] = __floats2bfloat162_rn(v.x, v.y);
    dst[i * 2 + 1] = __floats2bfloat162_rn(v.z, v.w);
}

__global__ void prep_w_kernel(const float* __restrict__ w1) {
    __shared__ float t[32][33];
    int n0 = blockIdx.x * 32, k0 = blockIdx.y * 32;
    int tx = threadIdx.x, ty = threadIdx.y;          // (32, 8)
    #pragma unroll
    for (int i = 0; i < 4; i++)
        t[ty + 8 * i][tx] = w1[(size_t)(k0 + ty + 8 * i) * HF + n0 + tx];
    __syncthreads();
    #pragma unroll
    for (int i = 0; i < 4; i++)
        g_w1b[(size_t)(n0 + ty + 8 * i) * DF + k0 + tx] =
            __float2bfloat16(t[tx][ty + 8 * i]);
}

// ---------------------------------------------------------------------------
// Kernel 1: fused filtration via bf16 mma.sync.m16n8k16, 4-stage cp.async.
//   f[n] = sigmoid( sum_c relu( x[n].W1[:,c] + b1[c] ) * w2[c] + b2 )
// CTA: 64 rows; 8 tiles of 128 channels; K chunks of 64 bf16 (=128B rows,
// SW128-style XOR swizzle). 8 warps = 2(M) x 4(N), warp tile 32x32.
// All fragments via ldmatrix.x4. h never materialized.
// ---------------------------------------------------------------------------
#define MT    64
#define CTW   128
#define KC    64                        // bf16 elements per chunk (128 B/row)
#define NCHUNK 64                       // (HF/CTW) * (DF/KC) = 8 * 8
#define STAGE_A_BYTES (MT*128)          // 8192
#define STAGE_B_BYTES (CTW*128)         // 16384
#define STAGE_BYTES   (STAGE_A_BYTES + STAGE_B_BYTES)   // 24576
#define NSTAGE 4
#define PFD    3
#define RED_OFF (NSTAGE*STAGE_BYTES)    // 98304
#define FILT_SMEM_BYTES (RED_OFF + MT*4*4)              // 99328

__device__ __forceinline__ void filt_issue_chunk(
    int rowbase, int tid, uint32_t sbase, int chunk)
{
    const int st = chunk & (NSTAGE - 1);
    const int ct = (chunk >> 3) * CTW;
    const int k0 = (chunk & 7) * KC;
    uint32_t ab = sbase + st * STAGE_BYTES;
    #pragma unroll
    for (int r = 0; r < 2; r++) {                 // A: 64 rows x 128B, swizzled
        int idx = tid + r * 256;
        int m   = idx >> 3;
        int seg = idx & 7;
        uint32_t dst = ab + (uint32_t)(m * 128 + ((seg * 16) ^ ((m & 7) * 16)));
        const void* src = &g_xb[(size_t)(rowbase + m) * DF + k0 + seg * 8];
        asm volatile("cp.async.cg.shared.global [%0], [%1], 16;" :: "r"(dst), "l"(src));
    }
    uint32_t bb = ab + STAGE_A_BYTES;
    #pragma unroll
    for (int r = 0; r < 4; r++) {                 // B: 128 chan x 128B, swizzled
        int idx = tid + r * 256;
        int n   = idx >> 3;
        int seg = idx & 7;
        uint32_t dst = bb + (uint32_t)(n * 128 + ((seg * 16) ^ ((n & 7) * 16)));
        const void* src = &g_w1b[(size_t)(ct + n) * DF + k0 + seg * 8];
        asm volatile("cp.async.cg.shared.global [%0], [%1], 16;" :: "r"(dst), "l"(src));
    }
    asm volatile("cp.async.commit_group;");
}

__global__ __launch_bounds__(256, 2) void filt_kernel(
    const float* __restrict__ b1, const float* __restrict__ w2,
    const float* __restrict__ b2)
{
    extern __shared__ uint8_t smem[];
    uint32_t sbase = (uint32_t)__cvta_generic_to_shared(smem);

    const int tid  = threadIdx.x;
    const int lane = tid & 31;
    const int warp = tid >> 5;
    const int wm   = warp >> 2;          // 0..1 (M)
    const int wn   = warp & 3;           // 0..3 (N)
    const int g    = lane >> 2;
    const int t4   = lane & 3;
    const int rowbase = blockIdx.x * MT;

    // ldmatrix lane addressing.
    // A (per mt): x4 matrices = (rows+0,klo),(rows+8,klo),(rows+0,khi),(rows+8,khi)
    //   lane: j=lane>>3 -> row += (j&1)*8, seg += (j>>1)
    // B (per pair p of n-tiles): x4 = (nt0,klo),(nt0,khi),(nt1,klo),(nt1,khi)
    //   lane: j -> nt += (j>>1), seg += (j&1)
    const int aj = lane >> 3;
    const int ar = lane & 7;
    int arow128[2], asw[2];
    #pragma unroll
    for (int mt = 0; mt < 2; mt++) {
        int row = wm * 32 + mt * 16 + ar + ((aj & 1) << 3);
        arow128[mt] = row * 128;
        asw[mt]     = row & 7;
    }
    const int ajhi = aj >> 1;
    int brow128[2], bsw[2];
    #pragma unroll
    for (int p = 0; p < 2; p++) {
        int row = wn * 32 + (p * 2 + (aj >> 1)) * 8 + ar;
        brow128[p] = row * 128;
        bsw[p]     = row & 7;
    }
    const int bjlo = aj & 1;

    filt_issue_chunk(rowbase, tid, sbase, 0);
    filt_issue_chunk(rowbase, tid, sbase, 1);
    filt_issue_chunk(rowbase, tid, sbase, 2);

    float c[2][4][4];
    float facc_lo[2] = {0.f, 0.f}, facc_hi[2] = {0.f, 0.f};

    for (int chunk = 0; chunk < NCHUNK; chunk++) {
        if ((chunk & 7) == 0) {
            #pragma unroll
            for (int mt = 0; mt < 2; mt++)
                #pragma unroll
                for (int nt = 0; nt < 4; nt++)
                    #pragma unroll
                    for (int j = 0; j < 4; j++) c[mt][nt][j] = 0.f;
        }
        if (chunk < NCHUNK - 2)       asm volatile("cp.async.wait_group 2;");
        else if (chunk == NCHUNK - 2) asm volatile("cp.async.wait_group 1;");
        else                          asm volatile("cp.async.wait_group 0;");
        __syncthreads();
        if (chunk + PFD < NCHUNK)
            filt_issue_chunk(rowbase, tid, sbase, chunk + PFD);

        const uint32_t sA = sbase + (chunk & (NSTAGE - 1)) * STAGE_BYTES;
        const uint32_t sB = sA + STAGE_A_BYTES;

        #pragma unroll
        for (int ks = 0; ks < 4; ks++) {             // 4 k-steps of 16
            uint32_t a[2][4], b[2][4];
            #pragma unroll
            for (int mt = 0; mt < 2; mt++) {
                uint32_t addr = sA + arow128[mt]
                    + (uint32_t)(((ks * 2 + ajhi) ^ asw[mt]) * 16);
                asm volatile(
                    "ldmatrix.sync.aligned.m8n8.x4.shared.b16 {%0,%1,%2,%3}, [%4];"
                    : "=r"(a[mt][0]), "=r"(a[mt][1]), "=r"(a[mt][2]), "=r"(a[mt][3])
                    : "r"(addr));
            }
            #pragma unroll
            for (int p = 0; p < 2; p++) {
                uint32_t addr = sB + brow128[p]
                    + (uint32_t)(((ks * 2 + bjlo) ^ bsw[p]) * 16);
                asm volatile(
                    "ldmatrix.sync.aligned.m8n8.x4.shared.b16 {%0,%1,%2,%3}, [%4];"
                    : "=r"(b[p][0]), "=r"(b[p][1]), "=r"(b[p][2]), "=r"(b[p][3])
                    : "r"(addr));
            }
            #pragma unroll
            for (int mt = 0; mt < 2; mt++)
                #pragma unroll
                for (int nt = 0; nt < 4; nt++)
                    asm volatile(
                        "mma.sync.aligned.m16n8k16.row.col.f32.bf16.bf16.f32 "
                        "{%0,%1,%2,%3}, {%4,%5,%6,%7}, {%8,%9}, {%0,%1,%2,%3};"
                        : "+f"(c[mt][nt][0]), "+f"(c[mt][nt][1]),
                          "+f"(c[mt][nt][2]), "+f"(c[mt][nt][3])
                        : "r"(a[mt][0]), "r"(a[mt][1]), "r"(a[mt][2]), "r"(a[mt][3]),
                          "r"(b[nt >> 1][(nt & 1) * 2]), "r"(b[nt >> 1][(nt & 1) * 2 + 1]));
        }

        if ((chunk & 7) == 7) {              // tile epilogue, registers only
            int ct = (chunk >> 3) * CTW;
            #pragma unroll
            for (int mt = 0; mt < 2; mt++) {
                float s_lo = 0.f, s_hi = 0.f;
                #pragma unroll
                for (int nt = 0; nt < 4; nt++) {
                    int col = ct + wn * 32 + nt * 8 + 2 * t4;
                    float bb0 = __ldg(&b1[col]),   bb1 = __ldg(&b1[col + 1]);
                    float w20 = __ldg(&w2[col]),   w21 = __ldg(&w2[col + 1]);
                    s_lo += fmaxf(c[mt][nt][0] + bb0, 0.f) * w20
                          + fmaxf(c[mt][nt][1] + bb1, 0.f) * w21;
                    s_hi += fmaxf(c[mt][nt][2] + bb0, 0.f) * w20
                          + fmaxf(c[mt][nt][3] + bb1, 0.f) * w21;
                }
                facc_lo[mt] += s_lo;
                facc_hi[mt] += s_hi;
            }
        }
    }

    float (*red)[4] = (float (*)[4])(smem + RED_OFF);
    #pragma unroll
    for (int mt = 0; mt < 2; mt++) {
        float slo = facc_lo[mt], shi = facc_hi[mt];
        slo += __shfl_xor_sync(0xFFFFFFFFu, slo, 1);
        slo += __shfl_xor_sync(0xFFFFFFFFu, slo, 2);
        shi += __shfl_xor_sync(0xFFFFFFFFu, shi, 1);
        shi += __shfl_xor_sync(0xFFFFFFFFu, shi, 2);
        if (t4 == 0) {
            int r0 = wm * 32 + mt * 16 + g;
            red[r0][wn]     = slo;
            red[r0 + 8][wn] = shi;
        }
    }
    __syncthreads();
    if (tid < MT) {
        float t = red[tid][0] + red[tid][1] + red[tid][2] + red[tid][3] + b2[0];
        g_f[rowbase + tid] = 1.f / (1.f + expf(-t));
    }
}

// ---------------------------------------------------------------------------
// Kernel 2: per-(graph, sign) persistence.
// Boruvka MSF (parallel, smem) -> sort <=255 MST edges -> serial elder-rule
// Kruskal over MST edges only. Fused phi-MLP pooling.  (unchanged)
// ---------------------------------------------------------------------------
__device__ __forceinline__ unsigned int f2ord(float f) {
    unsigned int b = __float_as_uint(f);
    return b ^ (((int)b >> 31) | 0x80000000u);
}
__device__ __forceinline__ float ord2f(unsigned int o) {
    unsigned int b = (o & 0x80000000u) ? (o ^ 0x80000000u) : ~o;
    return __uint_as_float(b);
}

__global__ __launch_bounds__(256) void persist_kernel(
    const int* __restrict__ edges,
    const float* __restrict__ w_phi0, const float* __restrict__ b_phi0,
    const float* __restrict__ w_phi1, const float* __restrict__ b_phi1)
{
    __shared__ float gf[NPG];
    __shared__ int   euv[EPG];
    __shared__ float ew[EPG];
    __shared__ unsigned long long ekey[EPG];
    __shared__ unsigned long long minE[NPG];
    __shared__ int   parent[NPG];
    __shared__ int   parent2[NPG];
    __shared__ unsigned char mst[EPG];
    __shared__ unsigned long long mlist[NPG];
    __shared__ float death[NPG];
    __shared__ unsigned char paired[NPG];
    __shared__ unsigned int  cmax[NPG];
    __shared__ float bs[NPG], ds[NPG];
    __shared__ int sh_changed, sh_nf, sh_cnt;

    const int tid = threadIdx.x;
    const int g   = blockIdx.x;
    const int s   = blockIdx.y;
    const float sign = s ? -1.f : 1.f;

    gf[tid]     = sign * g_f[g * NPG + tid];
    parent[tid] = tid;
    death[tid]  = 0.f;
    paired[tid] = 0;
    cmax[tid]   = 0u;
    __syncthreads();

    #pragma unroll
    for (int r = 0; r < 4; r++) {
        int e = tid + r * 256;
        int u = edges[(size_t)(g * EPG + e) * 2 + 0] & (NPG - 1);
        int v = edges[(size_t)(g * EPG + e) * 2 + 1] & (NPG - 1);
        float w = fmaxf(gf[u], gf[v]);
        euv[e]  = (u << 16) | v;
        ew[e]   = w;
        ekey[e] = ((unsigned long long)f2ord(w) << 32) | (unsigned int)e;
        mst[e]  = 0;
    }
    __syncthreads();

    for (int round = 0; round < 10; round++) {
        minE[tid] = ~0ull;
        if (tid == 0) sh_changed = 0;
        __syncthreads();

        #pragma unroll
        for (int r = 0; r < 4; r++) {
            int e  = tid + r * 256;
            int uv = euv[e];
            int ru = parent[uv >> 16], rv = parent[uv & 0xFFFF];
            if (ru != rv) {
                unsigned long long k = ekey[e];
                atomicMin(&minE[ru], k);
                atomicMin(&minE[rv], k);
            }
        }
        parent2[tid] = parent[tid];            // snapshot for link phase
        __syncthreads();

        if (parent2[tid] == tid) {
            unsigned long long mk = minE[tid];
            if (mk != ~0ull) {
                int e  = (int)(mk & 0xFFFFFFFFu);
                int uv = euv[e];
                int ru = parent2[uv >> 16], rv = parent2[uv & 0xFFFF];
                int other = (ru == tid) ? rv : ru;
                // break mutual-pair 2-cycle: smaller root id yields
                if (!((minE[other] == mk) && (other < tid))) {
                    parent[tid] = other;
                    mst[e] = 1;
                    sh_changed = 1;
                }
            }
        }
        __syncthreads();
        if (!sh_changed) break;

        for (;;) {                             // flatten until stable
            int pp = parent[tid];
            int p  = parent[pp];
            if (tid == 0) sh_nf = 0;
            __syncthreads();
            parent[tid] = p;
            if (p != pp) sh_nf = 1;
            __syncthreads();
            if (!sh_nf) break;
        }
    }

    if (tid == 0) sh_cnt = 0;
    __syncthreads();
    #pragma unroll
    for (int r = 0; r < 4; r++) {
        int e = tid + r * 256;
        if (mst[e]) mlist[atomicAdd(&sh_cnt, 1)] = ekey[e];
    }
    __syncthreads();
    const int cnt = sh_cnt;                    // <= 255
    if (tid >= cnt) mlist[tid] = ~0ull;
    parent[tid] = tid;                         // reset for Kruskal
    __syncthreads();

    for (int k = 2; k <= NPG; k <<= 1) {
        for (int j = k >> 1; j > 0; j >>= 1) {
            int p = tid ^ j;
            if (p > tid) {
                bool up = ((tid & k) == 0);
                unsigned long long a = mlist[tid], b = mlist[p];
                if ((a > b) == up) { mlist[tid] = b; mlist[p] = a; }
            }
            __syncthreads();
        }
    }

    if (tid == 0) {
        for (int t = 0; t < cnt; t++) {
            int e  = (int)(mlist[t] & 0xFFFFFFFFu);
            int uv = euv[e];
            int u  = uv >> 16, v = uv & 0xFFFF;
            int ru = u, rv = v;
            for (;;) {                         // interleaved dual find (ILP)
                int pu = parent[ru], pv = parent[rv];
                if (pu == ru && pv == rv) break;
                ru = pu; rv = pv;
            }
            parent[u] = ru; parent[v] = rv;    // endpoint compression
            float fu = gf[ru], fv = gf[rv];
            bool ue   = (fu < fv) || (fu == fv && ru < rv);
            int elder = ue ? ru : rv;
            int young = ue ? rv : ru;
            parent[young] = elder;
            death[young]  = ew[e];
            paired[young] = 1;
        }
    }
    __syncthreads();

    #pragma unroll
    for (int it = 0; it < 8; it++) {           // full compression
        int p = parent[parent[tid]];
        __syncthreads();
        parent[tid] = p;
        __syncthreads();
    }

    atomicMax(&cmax[parent[tid]], f2ord(gf[tid]));
    __syncthreads();

    float dv = paired[tid] ? death[tid] : ord2f(cmax[parent[tid]]);
    if (s == 0) { bs[tid] = gf[tid]; ds[tid] = dv;       }
    else        { bs[tid] = -dv;     ds[tid] = -gf[tid]; }
    __syncthreads();

    const float* wp = s ? w_phi1 : w_phi0;
    const float* bp = s ? b_phi1 : b_phi0;
    float wb = wp[tid], wd = wp[HP + tid], bb = bp[tid];
    float acc = 0.f;
    #pragma unroll 4
    for (int v = 0; v < NPG; v++)
        acc += fmaxf(bs[v] * wb + ds[v] * wd + bb, 0.f);
    g_pool[s][g][tid] = acc;
}

// ---------------------------------------------------------------------------
// Kernel 3: head
// ---------------------------------------------------------------------------
__global__ void head_kernel(const float* __restrict__ w_head,
                            const float* __restrict__ b_head,
                            float* __restrict__ out)
{
    int g = blockIdx.x;
    int warp = threadIdx.x >> 5, lane = threadIdx.x & 31;
    if (warp >= NC) return;
    const float* p0 = g_pool[0][g];
    const float* p1 = g_pool[1][g];
    float acc = 0.f;
    #pragma unroll
    for (int k = lane; k < HP; k += 32) {
        acc += p0[k] * w_head[k * NC + warp];
        acc += p1[k] * w_head[(HP + k) * NC + warp];
    }
    #pragma unroll
    for (int o = 16; o > 0; o >>= 1) acc += __shfl_down_sync(0xFFFFFFFFu, acc, o);
    if (lane == 0) out[g * NC + warp] = acc + b_head[warp];
}

// ---------------------------------------------------------------------------
extern "C" void kernel_launch(void* const* d_in, const int* in_sizes, int n_in,
                              void* d_out, int out_size)
{
    const float* x     = (const float*)d_in[0];
    const int*   edges = (const int*)d_in[1];
    const float* w1  = (const float*)d_in[3];
    const float* b1  = (const float*)d_in[4];
    const float* w2  = (const float*)d_in[5];
    const float* b2  = (const float*)d_in[6];
    const float* wp0 = (const float*)d_in[7];
    const float* bp0 = (const float*)d_in[8];
    const float* wp1 = (const float*)d_in[9];
    const float* bp1 = (const float*)d_in[10];
    const float* wh  = (const float*)d_in[11];
    const float* bh  = (const float*)d_in[12];

    prep_x_kernel<<<(NN * DF / 4) / 256, 256>>>((const float4*)x);
    prep_w_kernel<<<dim3(HF / 32, DF / 32), dim3(32, 8)>>>(w1);

    cudaFuncSetAttribute(filt_kernel,
                         cudaFuncAttributeMaxDynamicSharedMemorySize,
                         FILT_SMEM_BYTES);
    filt_kernel<<<NN / MT, 256, FILT_SMEM_BYTES>>>(b1, w2, b2);

    persist_kernel<<<dim3(NG, 2), 256>>>(edges, wp0, bp0, wp1, bp1);
    head_kernel<<<NG, 320>>>(wh, bh, (float*)d_out);
}